// round 5
// baseline (speedup 1.0000x reference)
#include <cuda_runtime.h>
#include <math.h>

#define NU 100000
#define NI 50000
#define NN (NU + NI)            // 150000 nodes
#define DIM 64
#define NE 1250000
#define NALL (NN * DIM)         // 9,600,000 floats per embedding buffer

// Scratch (allocation-free): ~131 MB of __device__ globals.
// __align__(16): accessed as float4 / red.global.add.v4.f32.
__device__ __align__(16) float g_buf[2][NALL];   // ping-pong layer buffers
__device__ __align__(16) float g_acc[NALL];      // running accumulator
__device__ float g_deg[NN];                      // in-degree (float)
__device__ float g_norm[NE];                     // per-edge symmetric norm
__device__ int   g_soff[NE];                     // src*64 (int32 offsets)
__device__ int   g_doff[NE];                     // dst*64

// ---------------------------------------------------------------------------
// K0: buf0 = acc = concat(user, item); buf1 = 0; deg = 0
__global__ void k_init(const float* __restrict__ uw, const float* __restrict__ iw) {
    int i = blockIdx.x * blockDim.x + threadIdx.x;
    if (i < NALL) {
        int row = i >> 6;
        float v = (row < NU) ? uw[i] : iw[i - NU * DIM];
        g_buf[0][i] = v;
        g_acc[i]    = v;
        g_buf[1][i] = 0.0f;
    }
    if (i < NN) g_deg[i] = 0.0f;
}

// K1: in-degree count. edge_index is INT32 (JAX default x64-disabled demotes
// jnp.int64 -> int32). Bounds-guarded: out-of-range edges are skipped.
__global__ void k_deg(const int* __restrict__ ei) {
    int e = blockIdx.x * blockDim.x + threadIdx.x;
    if (e >= NE) return;
    int dst = ei[NE + e];
    if ((unsigned)dst < (unsigned)NN)
        atomicAdd(&g_deg[dst], 1.0f);
}

// K2: norm[e] = 1/(sqrt(deg[src])*sqrt(deg[dst])) with finite guard;
//     cache int32 row-offsets for the hot scatter loop.
__global__ void k_norm(const int* __restrict__ ei) {
    int e = blockIdx.x * blockDim.x + threadIdx.x;
    if (e >= NE) return;
    int src = ei[e];
    int dst = ei[NE + e];
    if ((unsigned)src >= (unsigned)NN || (unsigned)dst >= (unsigned)NN) {
        g_norm[e] = 0.0f; g_soff[e] = 0; g_doff[e] = 0;
        return;
    }
    float n = 1.0f / (sqrtf(g_deg[src]) * sqrtf(g_deg[dst]));
    if (!isfinite(n)) n = 0.0f;
    g_norm[e] = n;
    g_soff[e] = src << 6;
    g_doff[e] = dst << 6;
}

// K3/5/7: one layer: buf[par^1][dst] += norm * buf[par][src]
// 16 lanes per edge, one float4 chunk each -> coalesced 256B gather per edge,
// one red.global.add.v4.f32 per chunk (4x fewer RED ops than scalar atomics).
__global__ void k_scatter(int par) {
    unsigned tid = blockIdx.x * blockDim.x + threadIdx.x;
    unsigned e = tid >> 4;
    if (e >= NE) return;
    int c = (int)(tid & 15u) << 2;
    float n = g_norm[e];
    if (n == 0.0f) return;                 // zero-norm / invalid edges: no-op
    const float4 v = *reinterpret_cast<const float4*>(&g_buf[par][g_soff[e] + c]);
    float* p = &g_buf[par ^ 1][g_doff[e] + c];
    asm volatile(
        "{\n\t"
        ".reg .u64 pg;\n\t"
        "cvta.to.global.u64 pg, %0;\n\t"
        "red.global.add.v4.f32 [pg], {%1, %2, %3, %4};\n\t"
        "}"
        :: "l"(p), "f"(v.x * n), "f"(v.y * n), "f"(v.z * n), "f"(v.w * n)
        : "memory");
}

// K4/6: acc += buf[newb]; zero buf[newb^1] for next layer's scatter target
__global__ void k_addzero(int newb) {
    int i4 = blockIdx.x * blockDim.x + threadIdx.x;
    if (i4 * 4 >= NALL) return;
    float4* acc = reinterpret_cast<float4*>(g_acc);
    float4* src = reinterpret_cast<float4*>(g_buf[newb]);
    float4* zro = reinterpret_cast<float4*>(g_buf[newb ^ 1]);
    float4 a = acc[i4], s = src[i4];
    a.x += s.x; a.y += s.y; a.z += s.z; a.w += s.w;
    acc[i4] = a;
    zro[i4] = make_float4(0.f, 0.f, 0.f, 0.f);
}

// K8: out = (acc + buf[1]) / 4, written to all three output regions.
// Layout [all; user; item] == [all; all] since user/item rows are contiguous
// in the same order -> write out[i] and out[NALL + i], no branching.
__global__ void k_final(float* __restrict__ out) {
    int i4 = blockIdx.x * blockDim.x + threadIdx.x;
    if (i4 * 4 >= NALL) return;
    const float4* acc = reinterpret_cast<const float4*>(g_acc);
    const float4* lst = reinterpret_cast<const float4*>(g_buf[1]);
    float4 a = acc[i4], s = lst[i4];
    float4 v = make_float4(0.25f * (a.x + s.x), 0.25f * (a.y + s.y),
                           0.25f * (a.z + s.z), 0.25f * (a.w + s.w));
    reinterpret_cast<float4*>(out)[i4] = v;
    reinterpret_cast<float4*>(out + NALL)[i4] = v;
}

extern "C" void kernel_launch(void* const* d_in, const int* in_sizes, int n_in,
                              void* d_out, int out_size) {
    const int*   ei = (const int*)d_in[0];      // [2, NE] int32 (JAX x64 off)
    const float* uw = (const float*)d_in[1];    // [NU, 64]
    const float* iw = (const float*)d_in[2];    // [NI, 64]
    float*      out = (float*)d_out;            // [2*NALL] floats

    const int T = 256;
    int g_nall  = (NALL + T - 1) / T;
    int g_edge  = (NE + T - 1) / T;
    int g_scat  = (NE * 16 + T - 1) / T;
    int g_vec   = (NALL / 4 + T - 1) / T;

    k_init<<<g_nall, T>>>(uw, iw);
    k_deg<<<g_edge, T>>>(ei);
    k_norm<<<g_edge, T>>>(ei);

    k_scatter<<<g_scat, T>>>(0);   // layer 1: buf0 -> buf1
    k_addzero<<<g_vec, T>>>(1);    // acc += buf1; buf0 = 0
    k_scatter<<<g_scat, T>>>(1);   // layer 2: buf1 -> buf0
    k_addzero<<<g_vec, T>>>(0);    // acc += buf0; buf1 = 0
    k_scatter<<<g_scat, T>>>(0);   // layer 3: buf0 -> buf1

    k_final<<<g_vec, T>>>(out);    // out = (acc + buf1)/4, duplicated
}

// round 6
// speedup vs baseline: 1.7513x; 1.7513x over previous
#include <cuda_runtime.h>
#include <math.h>

#define NU 100000
#define NI 50000
#define NN (NU + NI)            // 150000 nodes
#define DIM 64
#define NE 1250000
#define NALL (NN * DIM)         // 9,600,000 floats per buffer

#define SCAN_B 1024
#define NBLK ((NN + SCAN_B - 1) / SCAN_B)   // 147

// Scratch (allocation-free): ~166 MB of __device__ globals.
__device__ __align__(16) float g_b[4][NALL];  // b0=emb, b1..b3 = layer outputs
__device__ int   g_degi[NN];                  // in-degree (int)
__device__ int   g_rowstart[NN + 1];          // CSR row offsets (by dst)
__device__ int   g_rowfill[NN];               // fill cursors
__device__ int   g_blocksum[NBLK];            // scan partials
__device__ int   g_csr_soff[NE];              // permuted src*64
__device__ float g_csr_norm[NE];              // permuted edge norm

// ---------------------------------------------------------------------------
// K0: b0 = concat(user, item); zero degree + fill cursors.
__global__ void k_init(const float* __restrict__ uw, const float* __restrict__ iw) {
    int i = blockIdx.x * blockDim.x + threadIdx.x;
    if (i < NALL) {
        int row = i >> 6;
        g_b[0][i] = (row < NU) ? uw[i] : iw[i - NU * DIM];
    }
    if (i < NN) { g_degi[i] = 0; g_rowfill[i] = 0; }
}

// K1: in-degree (int). edge_index is int32 (JAX x64-off).
__global__ void k_deg(const int* __restrict__ ei) {
    int e = blockIdx.x * blockDim.x + threadIdx.x;
    if (e >= NE) return;
    int dst = ei[NE + e];
    if ((unsigned)dst < (unsigned)NN) atomicAdd(&g_degi[dst], 1);
}

// K2a: per-1024-block exclusive scan of degrees; emit block sums.
__global__ void k_scan1() {
    __shared__ int s[SCAN_B];
    int i = blockIdx.x * SCAN_B + threadIdx.x;
    int v = (i < NN) ? g_degi[i] : 0;
    s[threadIdx.x] = v;
    __syncthreads();
    for (int off = 1; off < SCAN_B; off <<= 1) {
        int t = (threadIdx.x >= off) ? s[threadIdx.x - off] : 0;
        __syncthreads();
        s[threadIdx.x] += t;
        __syncthreads();
    }
    if (i < NN) g_rowstart[i] = s[threadIdx.x] - v;  // exclusive within block
    if (threadIdx.x == SCAN_B - 1) g_blocksum[blockIdx.x] = s[SCAN_B - 1];
}

// K2b: exclusive scan of the 147 block sums (single block).
__global__ void k_scan2() {
    __shared__ int s[NBLK];
    int t = threadIdx.x;
    if (t < NBLK) s[t] = g_blocksum[t];
    __syncthreads();
    if (t == 0) {
        int run = 0;
        for (int j = 0; j < NBLK; j++) { int x = s[j]; s[j] = run; run += x; }
    }
    __syncthreads();
    if (t < NBLK) g_blocksum[t] = s[t];
}

// K2c: add block offsets; set sentinel rowstart[NN] = NE.
__global__ void k_scan3() {
    int i = blockIdx.x * blockDim.x + threadIdx.x;
    if (i < NN) g_rowstart[i] += g_blocksum[i / SCAN_B];
    if (i == 0) g_rowstart[NN] = NE;
}

// K3: compute norms and fill CSR (per-row atomic cursor; order-free fp sum).
__global__ void k_fill(const int* __restrict__ ei) {
    int e = blockIdx.x * blockDim.x + threadIdx.x;
    if (e >= NE) return;
    int src = ei[e];
    int dst = ei[NE + e];
    if ((unsigned)dst >= (unsigned)NN) return;   // consistent with k_deg guard
    bool sok = (unsigned)src < (unsigned)NN;
    int ds = sok ? g_degi[src] : 0;
    int dd = g_degi[dst];
    float n = 0.0f;
    if (ds > 0 && dd > 0)
        n = 1.0f / (sqrtf((float)ds) * sqrtf((float)dd));
    int pos = g_rowstart[dst] + atomicAdd(&g_rowfill[dst], 1);
    g_csr_norm[pos] = n;
    g_csr_soff[pos] = sok ? (src << 6) : 0;
}

// K4/5/6: pull layer. One 16-lane group per dst row; each lane owns one
// float4 chunk. Loop over the row's edge list (2-way unrolled for MLP),
// accumulate in registers, single coalesced 256B store. Zero atomics.
__global__ void k_gather(int lin, int lout) {
    int g = blockIdx.x * 16 + (threadIdx.x >> 4);
    if (g >= NN) return;
    int lane = (threadIdx.x & 15) << 2;
    const float* __restrict__ in = g_b[lin];
    int p   = g_rowstart[g];
    int end = g_rowstart[g + 1];
    float ax = 0.f, ay = 0.f, az = 0.f, aw = 0.f;
    for (; p + 2 <= end; p += 2) {
        float n0 = g_csr_norm[p];
        float n1 = g_csr_norm[p + 1];
        int   s0 = g_csr_soff[p];
        int   s1 = g_csr_soff[p + 1];
        float4 v0 = *reinterpret_cast<const float4*>(&in[s0 + lane]);
        float4 v1 = *reinterpret_cast<const float4*>(&in[s1 + lane]);
        ax += n0 * v0.x; ay += n0 * v0.y; az += n0 * v0.z; aw += n0 * v0.w;
        ax += n1 * v1.x; ay += n1 * v1.y; az += n1 * v1.z; aw += n1 * v1.w;
    }
    if (p < end) {
        float n0 = g_csr_norm[p];
        int   s0 = g_csr_soff[p];
        float4 v0 = *reinterpret_cast<const float4*>(&in[s0 + lane]);
        ax += n0 * v0.x; ay += n0 * v0.y; az += n0 * v0.z; aw += n0 * v0.w;
    }
    *reinterpret_cast<float4*>(&g_b[lout][(g << 6) + lane]) =
        make_float4(ax, ay, az, aw);
}

// K7: out = (b0+b1+b2+b3)/4 -> written at [all] and again at [user;item]
// (identical contiguous layout, so out[i] and out[NALL+i]).
__global__ void k_final(float* __restrict__ out) {
    int i4 = blockIdx.x * blockDim.x + threadIdx.x;
    if (i4 * 4 >= NALL) return;
    const float4* b0 = reinterpret_cast<const float4*>(g_b[0]);
    const float4* b1 = reinterpret_cast<const float4*>(g_b[1]);
    const float4* b2 = reinterpret_cast<const float4*>(g_b[2]);
    const float4* b3 = reinterpret_cast<const float4*>(g_b[3]);
    float4 a = b0[i4], b = b1[i4], c = b2[i4], d = b3[i4];
    float4 v = make_float4(0.25f * (a.x + b.x + c.x + d.x),
                           0.25f * (a.y + b.y + c.y + d.y),
                           0.25f * (a.z + b.z + c.z + d.z),
                           0.25f * (a.w + b.w + c.w + d.w));
    reinterpret_cast<float4*>(out)[i4] = v;
    reinterpret_cast<float4*>(out + NALL)[i4] = v;
}

extern "C" void kernel_launch(void* const* d_in, const int* in_sizes, int n_in,
                              void* d_out, int out_size) {
    const int*   ei = (const int*)d_in[0];      // [2, NE] int32
    const float* uw = (const float*)d_in[1];    // [NU, 64]
    const float* iw = (const float*)d_in[2];    // [NI, 64]
    float*      out = (float*)d_out;            // [2*NALL] floats

    const int T = 256;
    int g_nall = (NALL + T - 1) / T;
    int g_edge = (NE + T - 1) / T;
    int g_node = (NN + T - 1) / T;
    int g_gath = (NN + 15) / 16;                // 16 groups per 256-thread block
    int g_vec  = (NALL / 4 + T - 1) / T;

    k_init<<<g_nall, T>>>(uw, iw);
    k_deg<<<g_edge, T>>>(ei);
    k_scan1<<<NBLK, SCAN_B>>>();
    k_scan2<<<1, 256>>>();
    k_scan3<<<g_node, T>>>();
    k_fill<<<g_edge, T>>>(ei);

    k_gather<<<g_gath, T>>>(0, 1);   // layer 1
    k_gather<<<g_gath, T>>>(1, 2);   // layer 2
    k_gather<<<g_gath, T>>>(2, 3);   // layer 3

    k_final<<<g_vec, T>>>(out);
}